// round 1
// baseline (speedup 1.0000x reference)
#include <cuda_runtime.h>
#include <math.h>

#define NN 50000
#define EE 800000
#define GG 64
#define SG_SMEM (2*128*132*4)

// ---------------- scratch (static device globals; no allocation) ----------------
__device__ int   g_cnt[2][NN];
__device__ int   g_row[2][NN+1];
__device__ int   g_cur[2][NN];
__device__ int   g_csr[2][EE];
__device__ float g_inv[2][NN];
__device__ float g_agg[6400000];      // [NN*128]
__device__ float g_h[2][6400000];     // ping-pong hidden buffers
__device__ float g_pool[GG*256];

// ---------------- zero counters + pooled ----------------
__global__ void zero_kernel() {
    int i = blockIdx.x * blockDim.x + threadIdx.x;
    if (i < 2*NN) ((int*)g_cnt)[i] = 0;
    if (i < GG*256) g_pool[i] = 0.f;
}

// ---------------- degree histogram ----------------
__global__ void count_kernel(const int* __restrict__ dst, int set) {
    int e = blockIdx.x * blockDim.x + threadIdx.x;
    if (e < EE) atomicAdd(&g_cnt[set][dst[e]], 1);
}

// ---------------- exclusive scan (one block per edge set) ----------------
__global__ void scan_kernel() {
    int set = blockIdx.x;
    __shared__ int wsum[32];
    __shared__ int s_carry;
    int tid = threadIdx.x, lane = tid & 31, wid = tid >> 5;
    if (tid == 0) s_carry = 0;
    __syncthreads();
    for (int base = 0; base < NN; base += 4096) {
        int v[4];
        int i0 = base + tid * 4;
        #pragma unroll
        for (int j = 0; j < 4; j++) { int i = i0 + j; v[j] = (i < NN) ? g_cnt[set][i] : 0; }
        int ts = v[0] + v[1] + v[2] + v[3];
        int x = ts;
        #pragma unroll
        for (int o = 1; o < 32; o <<= 1) { int y = __shfl_up_sync(0xffffffffu, x, o); if (lane >= o) x += y; }
        if (lane == 31) wsum[wid] = x;
        __syncthreads();
        if (wid == 0) {
            int w = wsum[lane];
            #pragma unroll
            for (int o = 1; o < 32; o <<= 1) { int y = __shfl_up_sync(0xffffffffu, w, o); if (lane >= o) w += y; }
            wsum[lane] = w;
        }
        __syncthreads();
        int carry = s_carry;
        int excl = carry + (wid ? wsum[wid-1] : 0) + (x - ts);
        #pragma unroll
        for (int j = 0; j < 4; j++) {
            int i = i0 + j;
            if (i < NN) {
                g_row[set][i] = excl;
                g_cur[set][i] = excl;
                g_inv[set][i] = 1.0f / (float)(v[j] > 0 ? v[j] : 1);
            }
            excl += v[j];
        }
        __syncthreads();
        if (tid == 0) s_carry = carry + wsum[31];
        __syncthreads();
    }
    if (threadIdx.x == 0) g_row[set][NN] = s_carry;
}

// ---------------- CSR fill ----------------
__global__ void fill_kernel(const int* __restrict__ src, const int* __restrict__ dst, int set) {
    int e = blockIdx.x * blockDim.x + threadIdx.x;
    if (e < EE) {
        int d = dst[e];
        int p = atomicAdd(&g_cur[set][d], 1);
        g_csr[set][p] = src[e];
    }
}

// ---------------- mean aggregation: warp per node, float4 per lane ----------------
__global__ void agg_kernel(const float* __restrict__ x, int set, float* __restrict__ out) {
    int gw = (blockIdx.x * blockDim.x + threadIdx.x) >> 5;
    int lane = threadIdx.x & 31;
    if (gw >= NN) return;
    int s = g_row[set][gw], e = g_row[set][gw+1];
    float ax = 0.f, ay = 0.f, az = 0.f, aw = 0.f;
    for (int b = s; b < e; b += 32) {
        int m = min(32, e - b);
        int sid = (lane < m) ? g_csr[set][b + lane] : 0;
        for (int j = 0; j < m; j++) {
            int sj = __shfl_sync(0xffffffffu, sid, j);
            const float4 v = *reinterpret_cast<const float4*>(x + (size_t)sj * 128 + lane * 4);
            ax += v.x; ay += v.y; az += v.z; aw += v.w;
        }
    }
    float inv = g_inv[set][gw];
    float4 r; r.x = ax*inv; r.y = ay*inv; r.z = az*inv; r.w = aw*inv;
    *reinterpret_cast<float4*>(out + (size_t)gw * 128 + lane * 4) = r;
}

// ---------------- fused SAGE linear: out = relu(A@Wl^T + X@Wr^T + b) ----------------
__global__ __launch_bounds__(512) void sage_gemm_kernel(
    const float* __restrict__ A, const float* __restrict__ X,
    const float* __restrict__ Wl, const float* __restrict__ Wr,
    const float* __restrict__ bias, float* __restrict__ out)
{
    extern __shared__ float sm[];
    float* sWl = sm;              // [128][132] transposed: sWl[k*132+h] = Wl[h][k]
    float* sWr = sm + 128 * 132;
    for (int idx = threadIdx.x; idx < 128 * 128; idx += blockDim.x) {
        int h = idx >> 7, k = idx & 127;
        sWl[k * 132 + h] = Wl[idx];
        sWr[k * 132 + h] = Wr[idx];
    }
    __syncthreads();
    int lane = threadIdx.x & 31, wid = threadIdx.x >> 5;
    int stride = (blockDim.x >> 5) * gridDim.x;
    float4 bv = *reinterpret_cast<const float4*>(bias + lane * 4);
    for (int row = blockIdx.x * (blockDim.x >> 5) + wid; row < NN; row += stride) {
        const float4 a4 = *reinterpret_cast<const float4*>(A + (size_t)row * 128 + lane * 4);
        const float4 x4 = *reinterpret_cast<const float4*>(X + (size_t)row * 128 + lane * 4);
        float4 acc = bv;
        #pragma unroll 4
        for (int kl = 0; kl < 32; kl++) {
            float av[4], xv[4];
            av[0] = __shfl_sync(0xffffffffu, a4.x, kl);
            av[1] = __shfl_sync(0xffffffffu, a4.y, kl);
            av[2] = __shfl_sync(0xffffffffu, a4.z, kl);
            av[3] = __shfl_sync(0xffffffffu, a4.w, kl);
            xv[0] = __shfl_sync(0xffffffffu, x4.x, kl);
            xv[1] = __shfl_sync(0xffffffffu, x4.y, kl);
            xv[2] = __shfl_sync(0xffffffffu, x4.z, kl);
            xv[3] = __shfl_sync(0xffffffffu, x4.w, kl);
            #pragma unroll
            for (int j = 0; j < 4; j++) {
                int k = kl * 4 + j;
                const float4 wl = *reinterpret_cast<const float4*>(sWl + k * 132 + lane * 4);
                const float4 wr = *reinterpret_cast<const float4*>(sWr + k * 132 + lane * 4);
                acc.x += av[j] * wl.x + xv[j] * wr.x;
                acc.y += av[j] * wl.y + xv[j] * wr.y;
                acc.z += av[j] * wl.z + xv[j] * wr.z;
                acc.w += av[j] * wl.w + xv[j] * wr.w;
            }
        }
        acc.x = fmaxf(acc.x, 0.f); acc.y = fmaxf(acc.y, 0.f);
        acc.z = fmaxf(acc.z, 0.f); acc.w = fmaxf(acc.w, 0.f);
        *reinterpret_cast<float4*>(out + (size_t)row * 128 + lane * 4) = acc;
    }
}

// ---------------- global add pool ----------------
__global__ void pool_kernel(const float* __restrict__ h, const int* __restrict__ batch, int coloff) {
    int idx = blockIdx.x * blockDim.x + threadIdx.x;
    if (idx >= NN * 32) return;
    int node = idx >> 5, c4 = idx & 31;
    int g = batch[node];
    const float4 v = *reinterpret_cast<const float4*>(h + (size_t)node * 128 + c4 * 4);
    float* d = g_pool + g * 256 + coloff + c4 * 4;
    atomicAdd(d + 0, v.x); atomicAdd(d + 1, v.y);
    atomicAdd(d + 2, v.z); atomicAdd(d + 3, v.w);
}

// ---------------- MLP head + log_softmax, one block per graph ----------------
__global__ void head_kernel(
    const float* __restrict__ W1, const float* __restrict__ b1,
    const float* __restrict__ W2, const float* __restrict__ b2,
    const float* __restrict__ W3, const float* __restrict__ b3,
    float* __restrict__ out)
{
    __shared__ float sp[256], sh1[128], sh2[64];
    int g = blockIdx.x, t = threadIdx.x;
    sp[t]       = g_pool[g * 256 + t];
    sp[t + 128] = g_pool[g * 256 + 128 + t];
    __syncthreads();
    float a = b1[t];
    const float* w = W1 + t * 256;
    for (int k = 0; k < 256; k++) a += sp[k] * w[k];
    sh1[t] = fmaxf(a, 0.f);
    __syncthreads();
    if (t < 64) {
        float a2 = b2[t];
        const float* w2 = W2 + t * 128;
        for (int k = 0; k < 128; k++) a2 += sh1[k] * w2[k];
        sh2[t] = fmaxf(a2, 0.f);
    }
    __syncthreads();
    if (t == 0) {
        float l0 = b3[0], l1 = b3[1];
        for (int k = 0; k < 64; k++) { l0 += sh2[k] * W3[k]; l1 += sh2[k] * W3[64 + k]; }
        float m = fmaxf(l0, l1);
        float lse = m + logf(expf(l0 - m) + expf(l1 - m));
        out[g * 2 + 0] = l0 - lse;
        out[g * 2 + 1] = l1 - lse;
    }
}

// ---------------- launch ----------------
extern "C" void kernel_launch(void* const* d_in, const int* in_sizes, int n_in,
                              void* d_out, int out_size) {
    const float* sc_x  = (const float*)d_in[0];
    const float* fc_x  = (const float*)d_in[1];
    const int*   sc_ei = (const int*)d_in[2];
    const int*   fc_ei = (const int*)d_in[3];
    const int*   batch = (const int*)d_in[4];
    const float* scWl1 = (const float*)d_in[5];
    const float* scWr1 = (const float*)d_in[6];
    const float* scb1  = (const float*)d_in[7];
    const float* scWl2 = (const float*)d_in[8];
    const float* scWr2 = (const float*)d_in[9];
    const float* scb2  = (const float*)d_in[10];
    const float* fcWl1 = (const float*)d_in[11];
    const float* fcWr1 = (const float*)d_in[12];
    const float* fcb1  = (const float*)d_in[13];
    const float* fcWl2 = (const float*)d_in[14];
    const float* fcWr2 = (const float*)d_in[15];
    const float* fcb2  = (const float*)d_in[16];
    const float* W1    = (const float*)d_in[17];
    const float* bh1   = (const float*)d_in[18];
    const float* W2    = (const float*)d_in[19];
    const float* bh2   = (const float*)d_in[20];
    const float* W3    = (const float*)d_in[21];
    const float* bh3   = (const float*)d_in[22];
    float* out = (float*)d_out;

    cudaFuncSetAttribute(sage_gemm_kernel, cudaFuncAttributeMaxDynamicSharedMemorySize, SG_SMEM);

    float *agg, *hbase;
    cudaGetSymbolAddress((void**)&agg,   g_agg);
    cudaGetSymbolAddress((void**)&hbase, g_h);
    float* h0 = hbase;
    float* h1 = hbase + (size_t)NN * 128;

    int eb = (EE + 255) / 256;
    int ab = (NN * 32 + 255) / 256;

    zero_kernel<<<(2*NN + 255) / 256, 256>>>();
    count_kernel<<<eb, 256>>>(sc_ei + EE, 0);
    count_kernel<<<eb, 256>>>(fc_ei + EE, 1);
    scan_kernel<<<2, 1024>>>();
    fill_kernel<<<eb, 256>>>(sc_ei, sc_ei + EE, 0);
    fill_kernel<<<eb, 256>>>(fc_ei, fc_ei + EE, 1);

    // sc branch
    agg_kernel<<<ab, 256>>>(sc_x, 0, agg);
    sage_gemm_kernel<<<148, 512, SG_SMEM>>>(agg, sc_x, scWl1, scWr1, scb1, h0);
    agg_kernel<<<ab, 256>>>(h0, 0, agg);
    sage_gemm_kernel<<<148, 512, SG_SMEM>>>(agg, h0, scWl2, scWr2, scb2, h1);
    pool_kernel<<<ab, 256>>>(h1, batch, 0);

    // fc branch
    agg_kernel<<<ab, 256>>>(fc_x, 1, agg);
    sage_gemm_kernel<<<148, 512, SG_SMEM>>>(agg, fc_x, fcWl1, fcWr1, fcb1, h0);
    agg_kernel<<<ab, 256>>>(h0, 1, agg);
    sage_gemm_kernel<<<148, 512, SG_SMEM>>>(agg, h0, fcWl2, fcWr2, fcb2, h1);
    pool_kernel<<<ab, 256>>>(h1, batch, 128);

    head_kernel<<<GG, 128>>>(W1, bh1, W2, bh2, W3, bh3, out);
}

// round 3
// speedup vs baseline: 2.4198x; 2.4198x over previous
#include <cuda_runtime.h>
#include <math.h>

#define NN 50000
#define EE 800000
#define GG 64
#define CH 512
#define NB ((NN + CH - 1) / CH)   // 98 chunks
#define SG_SMEM (2*128*132*4)

// ---------------- scratch (static device globals; no allocation) ----------------
__device__ int   g_cnt[2][NN];
__device__ int   g_row[2][NN+1];
__device__ int   g_cur[2][NN];
__device__ int   g_csr[2][EE];
__device__ float g_inv[2][NN];
__device__ int   g_bsum[2][128];
__device__ int   g_boff[2][128];
__device__ float g_agg[6400000];      // [NN*128]
__device__ float g_h[2][6400000];     // ping-pong hidden buffers
__device__ float g_pool[GG*256];

// ---------------- zero counters + pooled + row sentinel ----------------
__global__ void zero_kernel() {
    int i = blockIdx.x * blockDim.x + threadIdx.x;
    if (i < 2*NN) ((int*)g_cnt)[i] = 0;
    if (i < GG*256) g_pool[i] = 0.f;
    if (i == 0) { g_row[0][NN] = EE; g_row[1][NN] = EE; }
}

// ---------------- degree histogram ----------------
__global__ void count_kernel(const int* __restrict__ dst, int set) {
    int e = blockIdx.x * blockDim.x + threadIdx.x;
    if (e < EE) atomicAdd(&g_cnt[set][dst[e]], 1);
}

// ---------------- phase 1: per-chunk sums ----------------
__global__ void block_reduce_kernel() {     // grid = 2*NB, 256 threads
    int set = blockIdx.x / NB, b = blockIdx.x - set * NB;
    int tid = threadIdx.x;
    int n0 = b * CH + tid;
    int s = 0;
    if (n0 < NN) s += g_cnt[set][n0];
    if (n0 + 256 < NN && tid + 256 < CH) s += g_cnt[set][n0 + 256];
    #pragma unroll
    for (int o = 16; o > 0; o >>= 1) s += __shfl_down_sync(0xffffffffu, s, o);
    __shared__ int ws[8];
    if ((tid & 31) == 0) ws[tid >> 5] = s;
    __syncthreads();
    if (tid == 0) {
        int t = 0;
        #pragma unroll
        for (int w = 0; w < 8; w++) t += ws[w];
        g_bsum[set][b] = t;
    }
}

// ---------------- phase 2: scan chunk sums (1 block) ----------------
__global__ void bsum_scan_kernel() {        // 1 block, 256 threads
    __shared__ int s[2][129];
    int set = threadIdx.x >> 7, i = threadIdx.x & 127;
    int v = (i < NB) ? g_bsum[set][i] : 0;
    s[set][i] = v;
    __syncthreads();
    #pragma unroll
    for (int o = 1; o < 128; o <<= 1) {
        int t = (i >= o) ? s[set][i - o] : 0;
        __syncthreads();
        s[set][i] += t;
        __syncthreads();
    }
    g_boff[set][i] = s[set][i] - v;  // exclusive
}

// ---------------- phase 3: per-chunk scan, write row/cur/inv ----------------
__global__ void chunk_scan_kernel() {       // grid = 2*NB, 512 threads
    int set = blockIdx.x / NB, b = blockIdx.x - set * NB;
    int tid = threadIdx.x, lane = tid & 31, wid = tid >> 5;
    __shared__ int wsum[16];
    int n = b * CH + tid;
    int v = (n < NN) ? g_cnt[set][n] : 0;
    int x = v;
    #pragma unroll
    for (int o = 1; o < 32; o <<= 1) { int y = __shfl_up_sync(0xffffffffu, x, o); if (lane >= o) x += y; }
    if (lane == 31) wsum[wid] = x;
    __syncthreads();
    if (wid == 0 && lane < 16) {
        int w = wsum[lane];
        #pragma unroll
        for (int o = 1; o < 16; o <<= 1) { int y = __shfl_up_sync(0x0000ffffu, w, o); if (lane >= o) w += y; }
        wsum[lane] = w;
    }
    __syncthreads();
    int excl = g_boff[set][b] + (wid ? wsum[wid - 1] : 0) + (x - v);
    if (n < NN) {
        g_row[set][n] = excl;
        g_cur[set][n] = excl;
        g_inv[set][n] = 1.0f / (float)(v > 0 ? v : 1);
    }
}

// ---------------- CSR fill ----------------
__global__ void fill_kernel(const int* __restrict__ src, const int* __restrict__ dst, int set) {
    int e = blockIdx.x * blockDim.x + threadIdx.x;
    if (e < EE) {
        int d = dst[e];
        int p = atomicAdd(&g_cur[set][d], 1);
        g_csr[set][p] = src[e];
    }
}

// ---------------- mean aggregation: warp per node, float4 per lane ----------------
__global__ void agg_kernel(const float* __restrict__ x, int set, float* __restrict__ out) {
    int gw = (blockIdx.x * blockDim.x + threadIdx.x) >> 5;
    int lane = threadIdx.x & 31;
    if (gw >= NN) return;
    int s = g_row[set][gw], e = g_row[set][gw+1];
    float ax = 0.f, ay = 0.f, az = 0.f, aw = 0.f;
    for (int b = s; b < e; b += 32) {
        int m = min(32, e - b);
        int sid = (lane < m) ? g_csr[set][b + lane] : 0;
        for (int j = 0; j < m; j++) {
            int sj = __shfl_sync(0xffffffffu, sid, j);
            const float4 v = *reinterpret_cast<const float4*>(x + (size_t)sj * 128 + lane * 4);
            ax += v.x; ay += v.y; az += v.z; aw += v.w;
        }
    }
    float inv = g_inv[set][gw];
    float4 r; r.x = ax*inv; r.y = ay*inv; r.z = az*inv; r.w = aw*inv;
    *reinterpret_cast<float4*>(out + (size_t)gw * 128 + lane * 4) = r;
}

// ---------------- fused SAGE linear: out = relu(A@Wl^T + X@Wr^T + b) ----------------
// 4 rows per warp: each smem weight load feeds 32 FFMA -> FFMA-issue-bound.
__device__ __forceinline__ float fcomp(const float4& v, int j) {
    return j == 0 ? v.x : j == 1 ? v.y : j == 2 ? v.z : v.w;
}

__global__ __launch_bounds__(512) void sage_gemm_kernel(
    const float* __restrict__ A, const float* __restrict__ X,
    const float* __restrict__ Wl, const float* __restrict__ Wr,
    const float* __restrict__ bias, float* __restrict__ out)
{
    extern __shared__ float sm[];
    float* sWl = sm;              // [128][132] transposed: sWl[k*132+h] = Wl[h][k]
    float* sWr = sm + 128 * 132;
    for (int idx = threadIdx.x; idx < 128 * 128; idx += blockDim.x) {
        int h = idx >> 7, k = idx & 127;
        sWl[k * 132 + h] = Wl[idx];
        sWr[k * 132 + h] = Wr[idx];
    }
    __syncthreads();
    int lane = threadIdx.x & 31, wid = threadIdx.x >> 5;
    int nwarp = (blockDim.x >> 5) * gridDim.x;
    float4 bv = *reinterpret_cast<const float4*>(bias + lane * 4);
    // NN = 50000 divisible by 4 -> every 4-row group is full.
    for (int row0 = (blockIdx.x * (blockDim.x >> 5) + wid) * 4; row0 < NN; row0 += nwarp * 4) {
        const float4* Ap = reinterpret_cast<const float4*>(A + (size_t)row0 * 128) + lane;
        const float4* Xp = reinterpret_cast<const float4*>(X + (size_t)row0 * 128) + lane;
        float4 av4[4], xv4[4], c[4];
        #pragma unroll
        for (int r = 0; r < 4; r++) {
            av4[r] = Ap[r * 32];
            xv4[r] = Xp[r * 32];
            c[r] = bv;
        }
        #pragma unroll 4
        for (int kl = 0; kl < 32; kl++) {
            #pragma unroll
            for (int j = 0; j < 4; j++) {
                int k = kl * 4 + j;
                const float4 wl = *reinterpret_cast<const float4*>(sWl + k * 132 + lane * 4);
                const float4 wr = *reinterpret_cast<const float4*>(sWr + k * 132 + lane * 4);
                #pragma unroll
                for (int r = 0; r < 4; r++) {
                    float av = __shfl_sync(0xffffffffu, fcomp(av4[r], j), kl);
                    float xv = __shfl_sync(0xffffffffu, fcomp(xv4[r], j), kl);
                    c[r].x += av * wl.x + xv * wr.x;
                    c[r].y += av * wl.y + xv * wr.y;
                    c[r].z += av * wl.z + xv * wr.z;
                    c[r].w += av * wl.w + xv * wr.w;
                }
            }
        }
        float4* Op = reinterpret_cast<float4*>(out + (size_t)row0 * 128) + lane;
        #pragma unroll
        for (int r = 0; r < 4; r++) {
            c[r].x = fmaxf(c[r].x, 0.f); c[r].y = fmaxf(c[r].y, 0.f);
            c[r].z = fmaxf(c[r].z, 0.f); c[r].w = fmaxf(c[r].w, 0.f);
            Op[r * 32] = c[r];
        }
    }
}

// ---------------- global add pool ----------------
__global__ void pool_kernel(const float* __restrict__ h, const int* __restrict__ batch, int coloff) {
    int idx = blockIdx.x * blockDim.x + threadIdx.x;
    if (idx >= NN * 32) return;
    int node = idx >> 5, c4 = idx & 31;
    int g = batch[node];
    const float4 v = *reinterpret_cast<const float4*>(h + (size_t)node * 128 + c4 * 4);
    float* d = g_pool + g * 256 + coloff + c4 * 4;
    atomicAdd(d + 0, v.x); atomicAdd(d + 1, v.y);
    atomicAdd(d + 2, v.z); atomicAdd(d + 3, v.w);
}

// ---------------- MLP head + log_softmax, one block per graph ----------------
__global__ void head_kernel(
    const float* __restrict__ W1, const float* __restrict__ b1,
    const float* __restrict__ W2, const float* __restrict__ b2,
    const float* __restrict__ W3, const float* __restrict__ b3,
    float* __restrict__ out)
{
    __shared__ float sp[256], sh1[128], sh2[64];
    int g = blockIdx.x, t = threadIdx.x;
    sp[t]       = g_pool[g * 256 + t];
    sp[t + 128] = g_pool[g * 256 + 128 + t];
    __syncthreads();
    float a = b1[t];
    const float* w = W1 + t * 256;
    for (int k = 0; k < 256; k++) a += sp[k] * w[k];
    sh1[t] = fmaxf(a, 0.f);
    __syncthreads();
    if (t < 64) {
        float a2 = b2[t];
        const float* w2 = W2 + t * 128;
        for (int k = 0; k < 128; k++) a2 += sh1[k] * w2[k];
        sh2[t] = fmaxf(a2, 0.f);
    }
    __syncthreads();
    if (t == 0) {
        float l0 = b3[0], l1 = b3[1];
        for (int k = 0; k < 64; k++) { l0 += sh2[k] * W3[k]; l1 += sh2[k] * W3[64 + k]; }
        float m = fmaxf(l0, l1);
        float lse = m + logf(expf(l0 - m) + expf(l1 - m));
        out[g * 2 + 0] = l0 - lse;
        out[g * 2 + 1] = l1 - lse;
    }
}

// ---------------- launch ----------------
extern "C" void kernel_launch(void* const* d_in, const int* in_sizes, int n_in,
                              void* d_out, int out_size) {
    const float* sc_x  = (const float*)d_in[0];
    const float* fc_x  = (const float*)d_in[1];
    const int*   sc_ei = (const int*)d_in[2];
    const int*   fc_ei = (const int*)d_in[3];
    const int*   batch = (const int*)d_in[4];
    const float* scWl1 = (const float*)d_in[5];
    const float* scWr1 = (const float*)d_in[6];
    const float* scb1  = (const float*)d_in[7];
    const float* scWl2 = (const float*)d_in[8];
    const float* scWr2 = (const float*)d_in[9];
    const float* scb2  = (const float*)d_in[10];
    const float* fcWl1 = (const float*)d_in[11];
    const float* fcWr1 = (const float*)d_in[12];
    const float* fcb1  = (const float*)d_in[13];
    const float* fcWl2 = (const float*)d_in[14];
    const float* fcWr2 = (const float*)d_in[15];
    const float* fcb2  = (const float*)d_in[16];
    const float* W1    = (const float*)d_in[17];
    const float* bh1   = (const float*)d_in[18];
    const float* W2    = (const float*)d_in[19];
    const float* bh2   = (const float*)d_in[20];
    const float* W3    = (const float*)d_in[21];
    const float* bh3   = (const float*)d_in[22];
    float* out = (float*)d_out;

    cudaFuncSetAttribute(sage_gemm_kernel, cudaFuncAttributeMaxDynamicSharedMemorySize, SG_SMEM);

    float *agg, *hbase;
    cudaGetSymbolAddress((void**)&agg,   g_agg);
    cudaGetSymbolAddress((void**)&hbase, g_h);
    float* h0 = hbase;
    float* h1 = hbase + (size_t)NN * 128;

    int eb = (EE + 255) / 256;
    int ab = (NN * 32 + 255) / 256;

    zero_kernel<<<(2*NN + 255) / 256, 256>>>();
    count_kernel<<<eb, 256>>>(sc_ei + EE, 0);
    count_kernel<<<eb, 256>>>(fc_ei + EE, 1);
    block_reduce_kernel<<<2 * NB, 256>>>();
    bsum_scan_kernel<<<1, 256>>>();
    chunk_scan_kernel<<<2 * NB, CH>>>();
    fill_kernel<<<eb, 256>>>(sc_ei, sc_ei + EE, 0);
    fill_kernel<<<eb, 256>>>(fc_ei, fc_ei + EE, 1);

    // sc branch
    agg_kernel<<<ab, 256>>>(sc_x, 0, agg);
    sage_gemm_kernel<<<148, 512, SG_SMEM>>>(agg, sc_x, scWl1, scWr1, scb1, h0);
    agg_kernel<<<ab, 256>>>(h0, 0, agg);
    sage_gemm_kernel<<<148, 512, SG_SMEM>>>(agg, h0, scWl2, scWr2, scb2, h1);
    pool_kernel<<<ab, 256>>>(h1, batch, 0);

    // fc branch
    agg_kernel<<<ab, 256>>>(fc_x, 1, agg);
    sage_gemm_kernel<<<148, 512, SG_SMEM>>>(agg, fc_x, fcWl1, fcWr1, fcb1, h0);
    agg_kernel<<<ab, 256>>>(h0, 1, agg);
    sage_gemm_kernel<<<148, 512, SG_SMEM>>>(agg, h0, fcWl2, fcWr2, fcb2, h1);
    pool_kernel<<<ab, 256>>>(h1, batch, 128);

    head_kernel<<<GG, 128>>>(W1, bh1, W2, bh2, W3, bh3, out);
}

// round 4
// speedup vs baseline: 2.7790x; 1.1484x over previous
#include <cuda_runtime.h>
#include <math.h>
#include <stdint.h>

#define NN 50000
#define EE 800000
#define GG 64
#define CH 512
#define NB ((NN + CH - 1) / CH)   // 98 chunks
#define SG_SMEM (2*128*132*4)

// ---------------- scratch (static device globals; no allocation) ----------------
__device__ int   g_cnt[2][NN];
__device__ int   g_row[2][NN+1];
__device__ int   g_cur[2][NN];
__device__ int   g_csr[2][EE];
__device__ float g_inv[2][NN];
__device__ int   g_bsum[2][128];
__device__ int   g_boff[2][128];
__device__ float g_agg[2][6400000];   // per-branch aggregate
__device__ float g_hb[4][6400000];    // h0_sc, h0_fc, h1_sc, h1_fc
__device__ float g_pool[GG*256];

// ---------------- f32x2 helpers ----------------
__device__ __forceinline__ void ffma2(uint64_t& c, uint64_t a, uint64_t b) {
    asm("fma.rn.f32x2 %0, %1, %2, %0;" : "+l"(c) : "l"(a), "l"(b));
}
__device__ __forceinline__ uint64_t pack2(float lo, float hi) {
    uint64_t r; asm("mov.b64 %0, {%1, %2};" : "=l"(r) : "f"(lo), "f"(hi)); return r;
}
__device__ __forceinline__ uint64_t dup2(float v) {
    uint64_t r; asm("mov.b64 %0, {%1, %1};" : "=l"(r) : "f"(v)); return r;
}
__device__ __forceinline__ void unpack2(uint64_t p, float& lo, float& hi) {
    asm("mov.b64 {%0, %1}, %2;" : "=f"(lo), "=f"(hi) : "l"(p));
}

// ---------------- zero counters + pooled + row sentinel ----------------
__global__ void zero_kernel() {
    int i = blockIdx.x * blockDim.x + threadIdx.x;
    if (i < 2*NN) ((int*)g_cnt)[i] = 0;
    if (i < GG*256) g_pool[i] = 0.f;
    if (i == 0) { g_row[0][NN] = EE; g_row[1][NN] = EE; }
}

// ---------------- degree histogram (both sets) ----------------
__global__ void count_kernel(const int* __restrict__ dst0, const int* __restrict__ dst1) {
    int e = blockIdx.x * blockDim.x + threadIdx.x;
    if (e < EE)            atomicAdd(&g_cnt[0][dst0[e]], 1);
    else if (e < 2 * EE)   atomicAdd(&g_cnt[1][dst1[e - EE]], 1);
}

// ---------------- phase 1: per-chunk sums ----------------
__global__ void block_reduce_kernel() {     // grid = 2*NB, 256 threads
    int set = blockIdx.x / NB, b = blockIdx.x - set * NB;
    int tid = threadIdx.x;
    int n0 = b * CH + tid;
    int s = 0;
    if (n0 < NN) s += g_cnt[set][n0];
    if (n0 + 256 < NN && tid + 256 < CH) s += g_cnt[set][n0 + 256];
    #pragma unroll
    for (int o = 16; o > 0; o >>= 1) s += __shfl_down_sync(0xffffffffu, s, o);
    __shared__ int ws[8];
    if ((tid & 31) == 0) ws[tid >> 5] = s;
    __syncthreads();
    if (tid == 0) {
        int t = 0;
        #pragma unroll
        for (int w = 0; w < 8; w++) t += ws[w];
        g_bsum[set][b] = t;
    }
}

// ---------------- phase 2: scan chunk sums (1 block) ----------------
__global__ void bsum_scan_kernel() {        // 1 block, 256 threads
    __shared__ int s[2][129];
    int set = threadIdx.x >> 7, i = threadIdx.x & 127;
    int v = (i < NB) ? g_bsum[set][i] : 0;
    s[set][i] = v;
    __syncthreads();
    #pragma unroll
    for (int o = 1; o < 128; o <<= 1) {
        int t = (i >= o) ? s[set][i - o] : 0;
        __syncthreads();
        s[set][i] += t;
        __syncthreads();
    }
    g_boff[set][i] = s[set][i] - v;  // exclusive
}

// ---------------- phase 3: per-chunk scan, write row/cur/inv ----------------
__global__ void chunk_scan_kernel() {       // grid = 2*NB, 512 threads
    int set = blockIdx.x / NB, b = blockIdx.x - set * NB;
    int tid = threadIdx.x, lane = tid & 31, wid = tid >> 5;
    __shared__ int wsum[16];
    int n = b * CH + tid;
    int v = (n < NN) ? g_cnt[set][n] : 0;
    int x = v;
    #pragma unroll
    for (int o = 1; o < 32; o <<= 1) { int y = __shfl_up_sync(0xffffffffu, x, o); if (lane >= o) x += y; }
    if (lane == 31) wsum[wid] = x;
    __syncthreads();
    if (wid == 0 && lane < 16) {
        int w = wsum[lane];
        #pragma unroll
        for (int o = 1; o < 16; o <<= 1) { int y = __shfl_up_sync(0x0000ffffu, w, o); if (lane >= o) w += y; }
        wsum[lane] = w;
    }
    __syncthreads();
    int excl = g_boff[set][b] + (wid ? wsum[wid - 1] : 0) + (x - v);
    if (n < NN) {
        g_row[set][n] = excl;
        g_cur[set][n] = excl;
        g_inv[set][n] = 1.0f / (float)(v > 0 ? v : 1);
    }
}

// ---------------- CSR fill (both sets) ----------------
__global__ void fill_kernel(const int* __restrict__ ei0, const int* __restrict__ ei1) {
    int e = blockIdx.x * blockDim.x + threadIdx.x;
    if (e < EE) {
        int d = ei0[EE + e];
        int p = atomicAdd(&g_cur[0][d], 1);
        g_csr[0][p] = ei0[e];
    } else if (e < 2 * EE) {
        int ee = e - EE;
        int d = ei1[EE + ee];
        int p = atomicAdd(&g_cur[1][d], 1);
        g_csr[1][p] = ei1[ee];
    }
}

// ---------------- mean aggregation, BOTH branches: warp per node ----------------
__global__ void agg_pair_kernel(const float* __restrict__ x0, float* __restrict__ out0,
                                const float* __restrict__ x1, float* __restrict__ out1) {
    int gw = (blockIdx.x * blockDim.x + threadIdx.x) >> 5;
    int lane = threadIdx.x & 31;
    if (gw >= 2 * NN) return;
    int set = (gw >= NN) ? 1 : 0;
    int node = gw - set * NN;
    const float* x = set ? x1 : x0;
    float* out = set ? out1 : out0;
    int s = g_row[set][node], e = g_row[set][node + 1];
    float ax = 0.f, ay = 0.f, az = 0.f, aw = 0.f;
    for (int b = s; b < e; b += 32) {
        int m = min(32, e - b);
        int sid = (lane < m) ? g_csr[set][b + lane] : 0;
        for (int j = 0; j < m; j++) {
            int sj = __shfl_sync(0xffffffffu, sid, j);
            const float4 v = *reinterpret_cast<const float4*>(x + (size_t)sj * 128 + lane * 4);
            ax += v.x; ay += v.y; az += v.z; aw += v.w;
        }
    }
    float inv = g_inv[set][node];
    float4 r; r.x = ax*inv; r.y = ay*inv; r.z = az*inv; r.w = aw*inv;
    *reinterpret_cast<float4*>(out + (size_t)node * 128 + lane * 4) = r;
}

// ---------------- fused SAGE linear, BOTH branches: relu(A@Wl^T + X@Wr^T + b) ----------------
__device__ __forceinline__ float fcomp(const float4& v, int j) {
    return j == 0 ? v.x : j == 1 ? v.y : j == 2 ? v.z : v.w;
}

__global__ __launch_bounds__(512) void sage_gemm_pair_kernel(
    const float* __restrict__ A0, const float* __restrict__ X0,
    const float* __restrict__ Wl0, const float* __restrict__ Wr0,
    const float* __restrict__ b0, float* __restrict__ out0,
    const float* __restrict__ A1, const float* __restrict__ X1,
    const float* __restrict__ Wl1, const float* __restrict__ Wr1,
    const float* __restrict__ b1, float* __restrict__ out1)
{
    extern __shared__ float sm[];
    float* sWl = sm;              // [128][132] transposed: sWl[k*132+h] = Wl[h][k]
    float* sWr = sm + 128 * 132;
    int half = gridDim.x >> 1;    // blocks per branch
    int br = (blockIdx.x >= half) ? 1 : 0;
    int bid = blockIdx.x - br * half;
    const float* A  = br ? A1  : A0;
    const float* X  = br ? X1  : X0;
    const float* Wl = br ? Wl1 : Wl0;
    const float* Wr = br ? Wr1 : Wr0;
    const float* bias = br ? b1 : b0;
    float* out = br ? out1 : out0;

    for (int idx = threadIdx.x; idx < 128 * 128; idx += blockDim.x) {
        int h = idx >> 7, k = idx & 127;
        sWl[k * 132 + h] = Wl[idx];
        sWr[k * 132 + h] = Wr[idx];
    }
    __syncthreads();
    int lane = threadIdx.x & 31, wid = threadIdx.x >> 5;
    int nwarp = (blockDim.x >> 5) * half;
    float4 bv = *reinterpret_cast<const float4*>(bias + lane * 4);
    uint64_t bxy = pack2(bv.x, bv.y), bzw = pack2(bv.z, bv.w);

    for (int row0 = (bid * (blockDim.x >> 5) + wid) * 4; row0 < NN; row0 += nwarp * 4) {
        const float4* Ap = reinterpret_cast<const float4*>(A + (size_t)row0 * 128) + lane;
        const float4* Xp = reinterpret_cast<const float4*>(X + (size_t)row0 * 128) + lane;
        float4 av4[4], xv4[4];
        uint64_t cxy[4], czw[4];
        #pragma unroll
        for (int r = 0; r < 4; r++) {
            av4[r] = Ap[r * 32];
            xv4[r] = Xp[r * 32];
            cxy[r] = bxy; czw[r] = bzw;
        }
        #pragma unroll 4
        for (int kl = 0; kl < 32; kl++) {
            #pragma unroll
            for (int j = 0; j < 4; j++) {
                int k = kl * 4 + j;
                const uint64_t* wlp = reinterpret_cast<const uint64_t*>(sWl + k * 132 + lane * 4);
                const uint64_t* wrp = reinterpret_cast<const uint64_t*>(sWr + k * 132 + lane * 4);
                uint64_t wl_xy = wlp[0], wl_zw = wlp[1];
                uint64_t wr_xy = wrp[0], wr_zw = wrp[1];
                #pragma unroll
                for (int r = 0; r < 4; r++) {
                    float av = __shfl_sync(0xffffffffu, fcomp(av4[r], j), kl);
                    float xv = __shfl_sync(0xffffffffu, fcomp(xv4[r], j), kl);
                    uint64_t ap = dup2(av), xp = dup2(xv);
                    ffma2(cxy[r], ap, wl_xy);
                    ffma2(cxy[r], xp, wr_xy);
                    ffma2(czw[r], ap, wl_zw);
                    ffma2(czw[r], xp, wr_zw);
                }
            }
        }
        float4* Op = reinterpret_cast<float4*>(out + (size_t)row0 * 128) + lane;
        #pragma unroll
        for (int r = 0; r < 4; r++) {
            float4 c;
            unpack2(cxy[r], c.x, c.y);
            unpack2(czw[r], c.z, c.w);
            c.x = fmaxf(c.x, 0.f); c.y = fmaxf(c.y, 0.f);
            c.z = fmaxf(c.z, 0.f); c.w = fmaxf(c.w, 0.f);
            Op[r * 32] = c;
        }
    }
}

// ---------------- global add pool (both branches) ----------------
__global__ void pool_pair_kernel(const float* __restrict__ hsc, const float* __restrict__ hfc,
                                 const int* __restrict__ batch) {
    int idx = blockIdx.x * blockDim.x + threadIdx.x;
    if (idx >= 2 * NN * 32) return;
    int br = (idx >= NN * 32) ? 1 : 0;
    int li = idx - br * NN * 32;
    int node = li >> 5, c4 = li & 31;
    int g = batch[node];
    const float* h = br ? hfc : hsc;
    const float4 v = *reinterpret_cast<const float4*>(h + (size_t)node * 128 + c4 * 4);
    float* d = g_pool + g * 256 + br * 128 + c4 * 4;
    atomicAdd(d + 0, v.x); atomicAdd(d + 1, v.y);
    atomicAdd(d + 2, v.z); atomicAdd(d + 3, v.w);
}

// ---------------- MLP head + log_softmax, one block per graph ----------------
__global__ void head_kernel(
    const float* __restrict__ W1, const float* __restrict__ b1,
    const float* __restrict__ W2, const float* __restrict__ b2,
    const float* __restrict__ W3, const float* __restrict__ b3,
    float* __restrict__ out)
{
    __shared__ float sp[256], sh1[128], sh2[64];
    int g = blockIdx.x, t = threadIdx.x;
    sp[t]       = g_pool[g * 256 + t];
    sp[t + 128] = g_pool[g * 256 + 128 + t];
    __syncthreads();
    float a = b1[t];
    const float* w = W1 + t * 256;
    for (int k = 0; k < 256; k++) a += sp[k] * w[k];
    sh1[t] = fmaxf(a, 0.f);
    __syncthreads();
    if (t < 64) {
        float a2 = b2[t];
        const float* w2 = W2 + t * 128;
        for (int k = 0; k < 128; k++) a2 += sh1[k] * w2[k];
        sh2[t] = fmaxf(a2, 0.f);
    }
    __syncthreads();
    if (t == 0) {
        float l0 = b3[0], l1 = b3[1];
        for (int k = 0; k < 64; k++) { l0 += sh2[k] * W3[k]; l1 += sh2[k] * W3[64 + k]; }
        float m = fmaxf(l0, l1);
        float lse = m + logf(expf(l0 - m) + expf(l1 - m));
        out[g * 2 + 0] = l0 - lse;
        out[g * 2 + 1] = l1 - lse;
    }
}

// ---------------- launch ----------------
extern "C" void kernel_launch(void* const* d_in, const int* in_sizes, int n_in,
                              void* d_out, int out_size) {
    const float* sc_x  = (const float*)d_in[0];
    const float* fc_x  = (const float*)d_in[1];
    const int*   sc_ei = (const int*)d_in[2];
    const int*   fc_ei = (const int*)d_in[3];
    const int*   batch = (const int*)d_in[4];
    const float* scWl1 = (const float*)d_in[5];
    const float* scWr1 = (const float*)d_in[6];
    const float* scb1  = (const float*)d_in[7];
    const float* scWl2 = (const float*)d_in[8];
    const float* scWr2 = (const float*)d_in[9];
    const float* scb2  = (const float*)d_in[10];
    const float* fcWl1 = (const float*)d_in[11];
    const float* fcWr1 = (const float*)d_in[12];
    const float* fcb1  = (const float*)d_in[13];
    const float* fcWl2 = (const float*)d_in[14];
    const float* fcWr2 = (const float*)d_in[15];
    const float* fcb2  = (const float*)d_in[16];
    const float* W1    = (const float*)d_in[17];
    const float* bh1   = (const float*)d_in[18];
    const float* W2    = (const float*)d_in[19];
    const float* bh2   = (const float*)d_in[20];
    const float* W3    = (const float*)d_in[21];
    const float* bh3   = (const float*)d_in[22];
    float* out = (float*)d_out;

    cudaFuncSetAttribute(sage_gemm_pair_kernel, cudaFuncAttributeMaxDynamicSharedMemorySize, SG_SMEM);

    float *aggb, *hb;
    cudaGetSymbolAddress((void**)&aggb, g_agg);
    cudaGetSymbolAddress((void**)&hb,   g_hb);
    float* agg0 = aggb;
    float* agg1 = aggb + (size_t)6400000;
    float* h0sc = hb;
    float* h0fc = hb + (size_t)6400000;
    float* h1sc = hb + (size_t)2 * 6400000;
    float* h1fc = hb + (size_t)3 * 6400000;

    int eb2 = (2 * EE + 255) / 256;
    int ab2 = (2 * NN * 32 + 255) / 256;

    zero_kernel<<<(2*NN + 255) / 256, 256>>>();
    count_kernel<<<eb2, 256>>>(sc_ei + EE, fc_ei + EE);
    block_reduce_kernel<<<2 * NB, 256>>>();
    bsum_scan_kernel<<<1, 256>>>();
    chunk_scan_kernel<<<2 * NB, CH>>>();
    fill_kernel<<<eb2, 256>>>(sc_ei, fc_ei);

    // layer 1 (both branches)
    agg_pair_kernel<<<ab2, 256>>>(sc_x, agg0, fc_x, agg1);
    sage_gemm_pair_kernel<<<296, 512, SG_SMEM>>>(
        agg0, sc_x, scWl1, scWr1, scb1, h0sc,
        agg1, fc_x, fcWl1, fcWr1, fcb1, h0fc);

    // layer 2 (both branches)
    agg_pair_kernel<<<ab2, 256>>>(h0sc, agg0, h0fc, agg1);
    sage_gemm_pair_kernel<<<296, 512, SG_SMEM>>>(
        agg0, h0sc, scWl2, scWr2, scb2, h1sc,
        agg1, h0fc, fcWl2, fcWr2, fcb2, h1fc);

    pool_pair_kernel<<<ab2, 256>>>(h1sc, h1fc, batch);
    head_kernel<<<GG, 128>>>(W1, bh1, W2, bh2, W3, bh3, out);
}